// round 8
// baseline (speedup 1.0000x reference)
#include <cuda_runtime.h>
#include <cstdint>

// 2D Haar DWT, fp32, input (8, 64, 512, 512) -> 4x (8, 64, 256, 256)
// Output d_out = [ll | lh | hl | hh], each 8*64*256*256 floats.
//
// R8: R7's read/write phase separation scaled 4x. Block = 1024 threads,
// 32 KB smem staging. Phase 2 writes 8 KB contiguous per subband per block
// (256 threads per subband, warp-ordered STG.128 -> dense 4 KB runs).
// Same 1 GiB global traffic.

#define PLANES      512          // 8 * 64
#define IN_W        512
#define OUT_W       256
#define OUT_H       256
#define PLANE_IN_F4   (IN_W * 512 / 4)     // 65536 float4 per input plane
#define ROW_IN_F4     (IN_W / 4)           // 128 float4 per input row
#define PLANE_OUT_F2  (OUT_W * OUT_H / 2)  // 32768 float2 per output plane
#define ROW_OUT_F2    (OUT_W / 2)          // 128 float2 per output row
#define SUBBAND_ELEMS (PLANES * OUT_W * OUT_H)  // 33554432 floats per subband
#define SUBBAND_F4    (SUBBAND_ELEMS / 4)       // 8388608 float4 per subband

#define BLOCK_THR   1024

__global__ __launch_bounds__(BLOCK_THR)
void dwt2d_haar_kernel(const float4* __restrict__ x4,
                       float4* __restrict__ out4)   // base of d_out as float4
{
    __shared__ float2 s[4][BLOCK_THR];   // [subband][item-in-block], 32 KB

    unsigned tid  = threadIdx.x;
    unsigned item = blockIdx.x * BLOCK_THR + tid;
    // item == output float2 index within each subband (exact identity).

    // ---- Phase 1: load 2x4 patch, compute, stage to smem ----
    unsigned ox2 = item & (ROW_OUT_F2 - 1);         // 0..127
    unsigned t1  = item >> 7;
    unsigned oy  = t1 & (OUT_H - 1);                // 0..255
    unsigned p   = t1 >> 8;                         // 0..511

    unsigned in_base = p * PLANE_IN_F4 + (2u * oy) * ROW_IN_F4 + ox2;
    float4 r0 = __ldcg(&x4[in_base]);               // row 2y,   cols 4x..4x+3
    float4 r1 = __ldcg(&x4[in_base + ROW_IN_F4]);   // row 2y+1

    float a0 = r0.x, b0 = r0.y, c0 = r1.x, d0 = r1.y;
    float a1 = r0.z, b1 = r0.w, c1 = r1.z, d1 = r1.w;

    const float half = 0.5f;
    float2 vll, vlh, vhl, vhh;
    vll.x = (a0 + b0 + c0 + d0) * half;
    vll.y = (a1 + b1 + c1 + d1) * half;
    vlh.x = (c0 + d0 - a0 - b0) * half;
    vlh.y = (c1 + d1 - a1 - b1) * half;
    vhl.x = (b0 + d0 - a0 - c0) * half;
    vhl.y = (b1 + d1 - a1 - c1) * half;
    vhh.x = (a0 + d0 - b0 - c0) * half;
    vhh.y = (a1 + d1 - b1 - c1) * half;

    s[0][tid] = vll;
    s[1][tid] = vlh;
    s[2][tid] = vhl;
    s[3][tid] = vhh;

    __syncthreads();

    // ---- Phase 2: burst-emit. 256 threads per subband, 2x STG.128 each,
    // warp-consecutive addresses -> dense 4 KB runs, 8 KB per subband. ----
    unsigned sub = tid >> 8;            // 0..3
    unsigned idx = tid & 255u;          // 0..255

    // block owns float4 range [blockIdx.x*512, +512) in each subband
    unsigned base4 = blockIdx.x * 512u;
    float4* outp = out4 + (size_t)sub * SUBBAND_F4;

    const float4* srow = (const float4*)&s[sub][0];   // 512 float4 staged
    float4 v0 = srow[idx];
    float4 v1 = srow[idx + 256];

    outp[base4 + idx]       = v0;
    outp[base4 + 256 + idx] = v1;
}

extern "C" void kernel_launch(void* const* d_in, const int* in_sizes, int n_in,
                              void* d_out, int out_size)
{
    const float4* x4 = (const float4*)d_in[0];
    float4* out4 = (float4*)d_out;

    const unsigned total_threads = PLANES * OUT_H * ROW_OUT_F2;  // 16,777,216
    const unsigned grid = total_threads / BLOCK_THR;             // 16,384

    dwt2d_haar_kernel<<<grid, BLOCK_THR>>>(x4, out4);
}

// round 9
// speedup vs baseline: 1.0601x; 1.0601x over previous
#include <cuda_runtime.h>
#include <cstdint>

// 2D Haar DWT, fp32, input (8, 64, 512, 512) -> 4x (8, 64, 256, 256)
// Output d_out = [ll | lh | hl | hh], each 8*64*256*256 floats.
//
// R9: R7's read/write phase separation at the untested midpoint block size.
// Block = 512 threads (16 warps), 16 KB smem staging. Phase 2 writes 4 KB
// contiguous per subband per block (128 threads per subband, 2x STG.128
// each). Bracket: 256thr=155.7us best, 1024thr=164.9us regress.

#define PLANES      512          // 8 * 64
#define IN_W        512
#define OUT_W       256
#define OUT_H       256
#define PLANE_IN_F4   (IN_W * 512 / 4)     // 65536 float4 per input plane
#define ROW_IN_F4     (IN_W / 4)           // 128 float4 per input row
#define PLANE_OUT_F2  (OUT_W * OUT_H / 2)  // 32768 float2 per output plane
#define ROW_OUT_F2    (OUT_W / 2)          // 128 float2 per output row
#define SUBBAND_ELEMS (PLANES * OUT_W * OUT_H)  // 33554432 floats per subband
#define SUBBAND_F4    (SUBBAND_ELEMS / 4)       // 8388608 float4 per subband

#define BLOCK_THR   512

__global__ __launch_bounds__(BLOCK_THR)
void dwt2d_haar_kernel(const float4* __restrict__ x4,
                       float4* __restrict__ out4)   // base of d_out as float4
{
    __shared__ float2 s[4][BLOCK_THR];   // [subband][item-in-block], 16 KB

    unsigned tid  = threadIdx.x;
    unsigned item = blockIdx.x * BLOCK_THR + tid;
    // item == output float2 index within each subband (exact identity).

    // ---- Phase 1: load 2x4 patch, compute, stage to smem ----
    unsigned ox2 = item & (ROW_OUT_F2 - 1);         // 0..127
    unsigned t1  = item >> 7;
    unsigned oy  = t1 & (OUT_H - 1);                // 0..255
    unsigned p   = t1 >> 8;                         // 0..511

    unsigned in_base = p * PLANE_IN_F4 + (2u * oy) * ROW_IN_F4 + ox2;
    float4 r0 = __ldcg(&x4[in_base]);               // row 2y,   cols 4x..4x+3
    float4 r1 = __ldcg(&x4[in_base + ROW_IN_F4]);   // row 2y+1

    float a0 = r0.x, b0 = r0.y, c0 = r1.x, d0 = r1.y;
    float a1 = r0.z, b1 = r0.w, c1 = r1.z, d1 = r1.w;

    const float half = 0.5f;
    float2 vll, vlh, vhl, vhh;
    vll.x = (a0 + b0 + c0 + d0) * half;
    vll.y = (a1 + b1 + c1 + d1) * half;
    vlh.x = (c0 + d0 - a0 - b0) * half;
    vlh.y = (c1 + d1 - a1 - b1) * half;
    vhl.x = (b0 + d0 - a0 - c0) * half;
    vhl.y = (b1 + d1 - a1 - c1) * half;
    vhh.x = (a0 + d0 - b0 - c0) * half;
    vhh.y = (a1 + d1 - b1 - c1) * half;

    s[0][tid] = vll;
    s[1][tid] = vlh;
    s[2][tid] = vhl;
    s[3][tid] = vhh;

    __syncthreads();

    // ---- Phase 2: burst-emit. 128 threads per subband, 2x STG.128 each,
    // warp-consecutive addresses -> 4 KB contiguous per subband per block. ----
    unsigned sub = tid >> 7;            // 0..3
    unsigned idx = tid & 127u;          // 0..127

    // block owns float4 range [blockIdx.x*256, +256) in each subband
    unsigned base4 = blockIdx.x * 256u;
    float4* outp = out4 + (size_t)sub * SUBBAND_F4;

    const float4* srow = (const float4*)&s[sub][0];   // 256 float4 staged
    float4 v0 = srow[idx];
    float4 v1 = srow[idx + 128];

    outp[base4 + idx]       = v0;
    outp[base4 + 128 + idx] = v1;
}

extern "C" void kernel_launch(void* const* d_in, const int* in_sizes, int n_in,
                              void* d_out, int out_size)
{
    const float4* x4 = (const float4*)d_in[0];
    float4* out4 = (float4*)d_out;

    const unsigned total_threads = PLANES * OUT_H * ROW_OUT_F2;  // 16,777,216
    const unsigned grid = total_threads / BLOCK_THR;             // 32,768

    dwt2d_haar_kernel<<<grid, BLOCK_THR>>>(x4, out4);
}

// round 10
// speedup vs baseline: 1.0655x; 1.0052x over previous
#include <cuda_runtime.h>
#include <cstdint>

// 2D Haar DWT, fp32, input (8, 64, 512, 512) -> 4x (8, 64, 256, 256)
// Output d_out = [ll | lh | hl | hh], each 8*64*256*256 floats.
//
// R10 (final): best measured geometry (512-thr phase-separated, R9) with
// L1-bypass on both loads (__ldcg) and phase-2 burst stores (__stcg).
// DRAM pinned at 85-86% active across 7 configs -> at practical HBM
// ceiling for 1:1 R/W streaming; this combines all best/neutral elements.

#define PLANES      512          // 8 * 64
#define IN_W        512
#define OUT_W       256
#define OUT_H       256
#define PLANE_IN_F4   (IN_W * 512 / 4)     // 65536 float4 per input plane
#define ROW_IN_F4     (IN_W / 4)           // 128 float4 per input row
#define PLANE_OUT_F2  (OUT_W * OUT_H / 2)  // 32768 float2 per output plane
#define ROW_OUT_F2    (OUT_W / 2)          // 128 float2 per output row
#define SUBBAND_ELEMS (PLANES * OUT_W * OUT_H)  // 33554432 floats per subband
#define SUBBAND_F4    (SUBBAND_ELEMS / 4)       // 8388608 float4 per subband

#define BLOCK_THR   512

__global__ __launch_bounds__(BLOCK_THR)
void dwt2d_haar_kernel(const float4* __restrict__ x4,
                       float4* __restrict__ out4)   // base of d_out as float4
{
    __shared__ float2 s[4][BLOCK_THR];   // [subband][item-in-block], 16 KB

    unsigned tid  = threadIdx.x;
    unsigned item = blockIdx.x * BLOCK_THR + tid;
    // item == output float2 index within each subband (exact identity).

    // ---- Phase 1: load 2x4 patch (L1-bypass), compute, stage to smem ----
    unsigned ox2 = item & (ROW_OUT_F2 - 1);         // 0..127
    unsigned t1  = item >> 7;
    unsigned oy  = t1 & (OUT_H - 1);                // 0..255
    unsigned p   = t1 >> 8;                         // 0..511

    unsigned in_base = p * PLANE_IN_F4 + (2u * oy) * ROW_IN_F4 + ox2;
    float4 r0 = __ldcg(&x4[in_base]);               // row 2y,   cols 4x..4x+3
    float4 r1 = __ldcg(&x4[in_base + ROW_IN_F4]);   // row 2y+1

    float a0 = r0.x, b0 = r0.y, c0 = r1.x, d0 = r1.y;
    float a1 = r0.z, b1 = r0.w, c1 = r1.z, d1 = r1.w;

    const float half = 0.5f;
    float2 vll, vlh, vhl, vhh;
    vll.x = (a0 + b0 + c0 + d0) * half;
    vll.y = (a1 + b1 + c1 + d1) * half;
    vlh.x = (c0 + d0 - a0 - b0) * half;
    vlh.y = (c1 + d1 - a1 - b1) * half;
    vhl.x = (b0 + d0 - a0 - c0) * half;
    vhl.y = (b1 + d1 - a1 - c1) * half;
    vhh.x = (a0 + d0 - b0 - c0) * half;
    vhh.y = (a1 + d1 - b1 - c1) * half;

    s[0][tid] = vll;
    s[1][tid] = vlh;
    s[2][tid] = vhl;
    s[3][tid] = vhh;

    __syncthreads();

    // ---- Phase 2: burst-emit, L1-bypass stores. 128 threads per subband,
    // 2x STG.128 each, warp-consecutive -> 4 KB contiguous per subband. ----
    unsigned sub = tid >> 7;            // 0..3
    unsigned idx = tid & 127u;          // 0..127

    // block owns float4 range [blockIdx.x*256, +256) in each subband
    unsigned base4 = blockIdx.x * 256u;
    float4* outp = out4 + (size_t)sub * SUBBAND_F4;

    const float4* srow = (const float4*)&s[sub][0];   // 256 float4 staged
    float4 v0 = srow[idx];
    float4 v1 = srow[idx + 128];

    __stcg(&outp[base4 + idx],       v0);
    __stcg(&outp[base4 + 128 + idx], v1);
}

extern "C" void kernel_launch(void* const* d_in, const int* in_sizes, int n_in,
                              void* d_out, int out_size)
{
    const float4* x4 = (const float4*)d_in[0];
    float4* out4 = (float4*)d_out;

    const unsigned total_threads = PLANES * OUT_H * ROW_OUT_F2;  // 16,777,216
    const unsigned grid = total_threads / BLOCK_THR;             // 32,768

    dwt2d_haar_kernel<<<grid, BLOCK_THR>>>(x4, out4);
}

// round 11
// speedup vs baseline: 1.0702x; 1.0044x over previous
#include <cuda_runtime.h>
#include <cstdint>

// 2D Haar DWT, fp32, input (8, 64, 512, 512) -> 4x (8, 64, 256, 256)
// Output d_out = [ll | lh | hl | hh], each 8*64*256*256 floats.
//
// R11: phase-separated (best family, R10=154.8us) with TMA bulk stores.
// Phase 1: 2x LDG.128 (L1-bypass) + compute + stage 16 KB to smem.
// Phase 2: thread 0 issues 4x cp.async.bulk (4 KB per subband) -- densest
// possible write presentation to DRAM, zero STG issue on the SMSPs.
// wait_group.read only (writes drain async; stream sync guarantees landing).

#define PLANES      512          // 8 * 64
#define IN_W        512
#define OUT_W       256
#define OUT_H       256
#define PLANE_IN_F4   (IN_W * 512 / 4)     // 65536 float4 per input plane
#define ROW_IN_F4     (IN_W / 4)           // 128 float4 per input row
#define PLANE_OUT_F2  (OUT_W * OUT_H / 2)  // 32768 float2 per output plane
#define ROW_OUT_F2    (OUT_W / 2)          // 128 float2 per output row
#define SUBBAND_ELEMS (PLANES * OUT_W * OUT_H)  // 33554432 floats per subband

#define BLOCK_THR   512
#define SUB_BYTES   (BLOCK_THR * 8)        // 4096 bytes per subband per block

__global__ __launch_bounds__(BLOCK_THR)
void dwt2d_haar_kernel(const float4* __restrict__ x4,
                       float* __restrict__ out)     // base of d_out
{
    __shared__ float2 s[4][BLOCK_THR];   // [subband][item-in-block], 16 KB

    unsigned tid  = threadIdx.x;
    unsigned item = blockIdx.x * BLOCK_THR + tid;
    // item == output float2 index within each subband (exact identity).

    // ---- Phase 1: load 2x4 patch (L1-bypass), compute, stage to smem ----
    unsigned ox2 = item & (ROW_OUT_F2 - 1);         // 0..127
    unsigned t1  = item >> 7;
    unsigned oy  = t1 & (OUT_H - 1);                // 0..255
    unsigned p   = t1 >> 8;                         // 0..511

    unsigned in_base = p * PLANE_IN_F4 + (2u * oy) * ROW_IN_F4 + ox2;
    float4 r0 = __ldcg(&x4[in_base]);               // row 2y,   cols 4x..4x+3
    float4 r1 = __ldcg(&x4[in_base + ROW_IN_F4]);   // row 2y+1

    float a0 = r0.x, b0 = r0.y, c0 = r1.x, d0 = r1.y;
    float a1 = r0.z, b1 = r0.w, c1 = r1.z, d1 = r1.w;

    const float half = 0.5f;
    float2 vll, vlh, vhl, vhh;
    vll.x = (a0 + b0 + c0 + d0) * half;
    vll.y = (a1 + b1 + c1 + d1) * half;
    vlh.x = (c0 + d0 - a0 - b0) * half;
    vlh.y = (c1 + d1 - a1 - b1) * half;
    vhl.x = (b0 + d0 - a0 - c0) * half;
    vhl.y = (b1 + d1 - a1 - c1) * half;
    vhh.x = (a0 + d0 - b0 - c0) * half;
    vhh.y = (a1 + d1 - b1 - c1) * half;

    s[0][tid] = vll;
    s[1][tid] = vlh;
    s[2][tid] = vhl;
    s[3][tid] = vhh;

    __syncthreads();

    // ---- Phase 2: TMA bulk store, 4 KB contiguous per subband. ----
    if (tid == 0) {
        // Make generic-proxy smem writes visible to the async proxy.
        asm volatile("fence.proxy.async.shared::cta;" ::: "memory");

        // block owns float2 range [blockIdx.x*512, +512) in each subband
        size_t base_f = (size_t)blockIdx.x * (2u * BLOCK_THR);

        #pragma unroll
        for (int sub = 0; sub < 4; sub++) {
            float* gptr = out + (size_t)sub * SUBBAND_ELEMS + base_f;
            uint32_t saddr;
            asm("{ .reg .u64 t; cvta.to.shared.u64 t, %1; cvt.u32.u64 %0, t; }"
                : "=r"(saddr) : "l"(&s[sub][0]));
            asm volatile(
                "cp.async.bulk.global.shared::cta.bulk_group [%0], [%1], %2;"
                :: "l"(gptr), "r"(saddr), "r"((uint32_t)SUB_BYTES)
                : "memory");
        }
        asm volatile("cp.async.bulk.commit_group;" ::: "memory");
        // Wait only until smem has been read out; writes drain asynchronously.
        asm volatile("cp.async.bulk.wait_group.read 0;" ::: "memory");
    }
    // All threads must hold the CTA (and its smem) until read-out completes.
    __syncthreads();
}

extern "C" void kernel_launch(void* const* d_in, const int* in_sizes, int n_in,
                              void* d_out, int out_size)
{
    const float4* x4 = (const float4*)d_in[0];
    float* out = (float*)d_out;

    const unsigned total_threads = PLANES * OUT_H * ROW_OUT_F2;  // 16,777,216
    const unsigned grid = total_threads / BLOCK_THR;             // 32,768

    dwt2d_haar_kernel<<<grid, BLOCK_THR>>>(x4, out);
}